// round 13
// baseline (speedup 1.0000x reference)
#include <cuda_runtime.h>
#include <cuda_fp16.h>
#include <cstdint>

#define J 24
#define TFR 4096
#define BB 32
#define KS 15
#define NT 256

// ---- smem layout (bytes) ----
#define A_ROWS   272
#define A_PITCH  256                 // 128 ch * fp16
#define ASZ      (A_ROWS * A_PITCH)  // 69632
#define SMEM_W   ASZ                 // W ring / x-staging area
#define WT       8192                // per-tap pooled W: 128ch x 32n x fp16
#define SMEM_TOTAL (SMEM_W + 4 * WT)     // 102400 -> 2 CTAs/SM
#define STG_CH   8                   // staging chunk: 8 ch x 272 t fp32
#define STG_PITCH 1088               // 272 floats
#define STG_SZ   (STG_CH * STG_PITCH)    // 8704 B; 3-deep ring fits in 32 KB
#define EPI_PITCH 1040               // 260 f32

// scratch
__device__ __align__(16) __half g_wt[12 * KS * WT / 2];

// ---------------- helpers ----------------
__device__ __forceinline__ uint32_t smem_u32(const void* p) {
    uint32_t a;
    asm("{ .reg .u64 t; cvta.to.shared.u64 t, %1; cvt.u32.u64 %0, t; }" : "=r"(a) : "l"(p));
    return a;
}
__device__ __forceinline__ uint32_t pack_h2(float lo, float hi) {
    __half2 h = __floats2half2_rn(lo, hi);
    uint32_t u;
    asm("mov.b32 %0, %1;" : "=r"(u) : "r"(*reinterpret_cast<uint32_t*>(&h)));
    return u;
}
__device__ __forceinline__ void ldsm_x4(uint32_t* r, uint32_t a) {
    asm volatile("ldmatrix.sync.aligned.m8n8.x4.shared.b16 {%0,%1,%2,%3}, [%4];"
                 : "=r"(r[0]), "=r"(r[1]), "=r"(r[2]), "=r"(r[3]) : "r"(a));
}
__device__ __forceinline__ void ldsm_x4t(uint32_t* r, uint32_t a) {
    asm volatile("ldmatrix.sync.aligned.m8n8.x4.trans.shared.b16 {%0,%1,%2,%3}, [%4];"
                 : "=r"(r[0]), "=r"(r[1]), "=r"(r[2]), "=r"(r[3]) : "r"(a));
}
__device__ __forceinline__ void mma_f16(float* d, const uint32_t* a, uint32_t b0, uint32_t b1) {
    asm volatile("mma.sync.aligned.m16n8k16.row.col.f32.f16.f16.f32 "
                 "{%0,%1,%2,%3}, {%4,%5,%6,%7}, {%8,%9}, {%0,%1,%2,%3};"
                 : "+f"(d[0]), "+f"(d[1]), "+f"(d[2]), "+f"(d[3])
                 : "r"(a[0]), "r"(a[1]), "r"(a[2]), "r"(a[3]), "r"(b0), "r"(b1));
}
__device__ __forceinline__ void cp16(uint32_t dst, const void* src, uint32_t srcsz) {
    asm volatile("cp.async.cg.shared.global [%0], [%1], 16, %2;"
                 :: "r"(dst), "l"(src), "r"(srcsz) : "memory");
}
#define CP_COMMIT() asm volatile("cp.async.commit_group;" ::: "memory")
#define CP_WAITG(n) asm volatile("cp.async.wait_group %0;" :: "n"(n) : "memory")

__device__ __forceinline__ int iclamp(int v, int lo, int hi) {
    return v < lo ? lo : (v > hi ? hi : v);
}

// ---------------- pre-pass: pooled masked W -> fp16, [ch][n] swizzled ----------------
// W_pool[g][k][ch(128 union)][n(32)] = 0.5 * sum_h mask * w[(2g+h)*32+n][union_ch][k]
__global__ void wprep(const float* __restrict__ w) {
    int idx = blockIdx.x * 256 + threadIdx.x;
    const int total = 12 * KS * 128 * 32;
    if (idx >= total) return;
    int n = idx & 31;         idx >>= 5;
    int r = idx & 127;        idx >>= 7;
    int k = idx % KS;
    int g = idx / KS;
    int jb = iclamp(2 * g - 1, 0, J - 4);
    int ji = jb + (r >> 5), ci = r & 31;
    float v = 0.f;
    #pragma unroll
    for (int h = 0; h < 2; ++h) {
        int j = 2 * g + h;
        int d = ji - j;
        if (d >= -1 && d <= 1)
            v += 0.5f * w[((size_t)(j * 32 + n) * 768 + (size_t)(ji * 32 + ci)) * KS + k];
    }
    size_t off = (size_t)(g * KS + k) * WT
               + r * 64 + ((((uint32_t)n >> 3) ^ ((r >> 1) & 3)) << 4) + (n & 7) * 2;
    *reinterpret_cast<__half*>(reinterpret_cast<char*>(g_wt) + off) = __float2half_rn(v);
}

// ---------------- main: fused transpose + mma.sync pooled conv ----------------
__global__ void __launch_bounds__(NT, 2)
skel_mma(const float* __restrict__ x,
         const float* __restrict__ bias, float* __restrict__ out)
{
    extern __shared__ char smem[];
    const uint32_t sb = smem_u32(smem);
    const int tid = threadIdx.x;
    const int l = tid & 31, wrp = tid >> 5;   // warp owns frames [wrp*32, wrp*32+32)
    const int tt = blockIdx.x, g = blockIdx.y, b = blockIdx.z;
    const int t0 = tt * 256;

    const int jb = iclamp(2 * g - 1, 0, J - 4);
    const float* xb = x + ((size_t)b * 768 + (size_t)jb * 32) * TFR;

    // ---- prologue: stage fp32 x chunks, transpose+convert into fp16 A tile ----
    // chunk c = 8 ch x 272 t; staged via 3-deep cp.async ring in the W area.
    auto issue_chunk = [&](int c) {
        uint32_t stg = sb + SMEM_W + (c % 3) * STG_SZ;
        #pragma unroll 1
        for (int it2 = 0; it2 < 3; ++it2) {
            int i = it2 * NT + tid;            // need 0..543 (8 rows x 68 float4)
            if (i < 544) {
                int row = i / 68, u = i - row * 68;
                int t = t0 - 8 + 4 * u;
                uint32_t ok = (t >= 0 && t <= TFR - 4) ? 16u : 0u;
                cp16(stg + row * STG_PITCH + (u << 4),
                     xb + (size_t)(c * STG_CH + row) * TFR + t, ok);
            }
        }
        CP_COMMIT();
    };
    auto transpose_chunk = [&](int c) {
        const float* stg = reinterpret_cast<const float*>(smem + SMEM_W + (c % 3) * STG_SZ);
        #pragma unroll
        for (int rep = 0; rep < 2; ++rep) {
            int tl = rep * NT + tid;
            if (tl < A_ROWS) {
                float v[8];
                #pragma unroll
                for (int ci = 0; ci < 8; ++ci) v[ci] = stg[ci * 272 + tl];
                uint4 val;
                val.x = pack_h2(v[0], v[1]);
                val.y = pack_h2(v[2], v[3]);
                val.z = pack_h2(v[4], v[5]);
                val.w = pack_h2(v[6], v[7]);
                *reinterpret_cast<uint4*>(smem + tl * A_PITCH + ((c ^ (tl & 7)) << 4)) = val;
            }
        }
    };

    issue_chunk(0); issue_chunk(1); issue_chunk(2);
    #pragma unroll 1
    for (int c = 0; c < 14; ++c) {
        CP_WAITG(2);
        __syncthreads();
        transpose_chunk(c);
        __syncthreads();
        if (c + 3 < 16) issue_chunk(c + 3);
    }
    CP_WAITG(1); __syncthreads(); transpose_chunk(14); __syncthreads();
    CP_WAITG(0); __syncthreads(); transpose_chunk(15); __syncthreads();

    // ---- W taps 0..3 into the (now free) ring ----
    #pragma unroll
    for (int kk = 0; kk < 4; ++kk) {
        const char* wsrc = reinterpret_cast<const char*>(g_wt) + (size_t)(g * KS + kk) * WT;
        uint32_t wdst = sb + SMEM_W + kk * WT;
        #pragma unroll
        for (int c = 0; c < 2; ++c) {
            int i = c * NT + tid;
            cp16(wdst + i * 16, wsrc + (size_t)i * 16, 16u);
        }
    }
    CP_COMMIT();

    // per-lane constants
    const int row_off = (l & 7) + ((l >> 3) & 1) * 8;
    const int ca      = (l >> 4) & 1;
    const int bswz    = (row_off >> 1) & 3;
    const uint32_t b_lane0 = row_off * 64 + ((uint32_t)((0 + ca) ^ bswz) << 4);
    const uint32_t b_lane1 = row_off * 64 + ((uint32_t)((2 + ca) ^ bswz) << 4);

    auto ldB = [&](uint32_t* bf, uint32_t bst, int q) {
        ldsm_x4t(bf,     bst + q * 1024 + b_lane0);
        ldsm_x4t(bf + 4, bst + q * 1024 + b_lane1);
    };
    auto ldA = [&](uint32_t (*ah)[4], int kk, int q) {
        #pragma unroll
        for (int mi = 0; mi < 2; ++mi) {
            int row = wrp * 32 + mi * 16 + row_off + kk + 1;
            ldsm_x4(ah[mi], sb + row * A_PITCH
                    + ((uint32_t)((2 * q + ca) ^ (row & 7)) << 4));
        }
    };

    float acc[2][4][4];
    #pragma unroll
    for (int mi = 0; mi < 2; ++mi)
        #pragma unroll
        for (int jf = 0; jf < 4; ++jf)
            #pragma unroll
            for (int e = 0; e < 4; ++e) acc[mi][jf][e] = 0.f;

    // ---- tap loop: 2 taps per sync, 4-stage W ring, double-buffered frags ----
    #pragma unroll 1
    for (int k = 0; k < KS; k += 2) {
        CP_WAITG(0);
        __syncthreads();
        #pragma unroll
        for (int d = 2; d < 4; ++d) {
            int kk = k + d;
            if (kk < KS) {
                const char* wsrc = reinterpret_cast<const char*>(g_wt) + (size_t)(g * KS + kk) * WT;
                uint32_t wdst = sb + SMEM_W + (kk & 3) * WT;
                #pragma unroll
                for (int c = 0; c < 2; ++c) {
                    int i = c * NT + tid;
                    cp16(wdst + i * 16, wsrc + (size_t)i * 16, 16u);
                }
            }
        }
        CP_COMMIT();

        #pragma unroll 1
        for (int d = 0; d < 2; ++d) {
            int kk = k + d;
            if (kk >= KS) break;
            const uint32_t bst = sb + SMEM_W + (kk & 3) * WT;
            uint32_t bf[2][8], ah[2][2][4];
            ldB(bf[0], bst, 0);
            ldA(ah[0], kk, 0);
            #pragma unroll
            for (int q = 0; q < 8; ++q) {
                const int cur = q & 1;
                if (q < 7) { ldB(bf[cur ^ 1], bst, q + 1); ldA(ah[cur ^ 1], kk, q + 1); }
                #pragma unroll
                for (int mi = 0; mi < 2; ++mi)
                    #pragma unroll
                    for (int jf = 0; jf < 4; ++jf)
                        mma_f16(acc[mi][jf], ah[cur][mi], bf[cur][2 * jf], bf[cur][2 * jf + 1]);
            }
        }
    }

    // ---- epilogue: transpose through smem, bias + LeakyReLU, STG.128 ----
    __syncthreads();
    #pragma unroll
    for (int mi = 0; mi < 2; ++mi)
        #pragma unroll
        for (int jf = 0; jf < 4; ++jf)
            #pragma unroll
            for (int e = 0; e < 4; ++e) {
                int co = 8 * jf + 2 * (l & 3) + (e & 1);
                int fr = wrp * 32 + mi * 16 + (l >> 2) + 8 * (e >> 1);
                *reinterpret_cast<float*>(smem + co * EPI_PITCH + fr * 4) = acc[mi][jf][e];
            }
    __syncthreads();

    {
        int co = tid >> 3;                  // 0..31
        int fs = (tid & 7) * 32;            // 32 frames per thread
        float bsum = 0.5f * (bias[g * 64 + co] + bias[g * 64 + 32 + co]);
        float* obase = out + ((size_t)b * 384 + g * 32 + co) * TFR + t0 + fs;
        #pragma unroll
        for (int u = 0; u < 8; ++u) {
            float4 v = *reinterpret_cast<float4*>(smem + co * EPI_PITCH + (fs + 4 * u) * 4);
            float4 r;
            r.x = v.x + bsum;  r.y = v.y + bsum;
            r.z = v.z + bsum;  r.w = v.w + bsum;
            r.x = (r.x >= 0.f) ? r.x : 0.2f * r.x;
            r.y = (r.y >= 0.f) ? r.y : 0.2f * r.y;
            r.z = (r.z >= 0.f) ? r.z : 0.2f * r.z;
            r.w = (r.w >= 0.f) ? r.w : 0.2f * r.w;
            *reinterpret_cast<float4*>(obase + 4 * u) = r;
        }
    }
}

extern "C" void kernel_launch(void* const* d_in, const int* in_sizes, int n_in,
                              void* d_out, int out_size) {
    const float* x      = (const float*)d_in[0];  // [32, 768, 4096]
    const float* weight = (const float*)d_in[1];  // [768, 768, 15]
    const float* bias   = (const float*)d_in[2];  // [768]
    float* out = (float*)d_out;                   // [32, 384, 4096]

    const int wtotal = 12 * KS * 128 * 32;
    wprep<<<(wtotal + 255) / 256, 256>>>(weight);

    cudaFuncSetAttribute(skel_mma, cudaFuncAttributeMaxDynamicSharedMemorySize, SMEM_TOTAL);
    dim3 grid(TFR / 256, 12, BB);
    skel_mma<<<grid, NT, SMEM_TOTAL>>>(x, bias, out);
}